// round 11
// baseline (speedup 1.0000x reference)
#include <cuda_runtime.h>
#include <cstdint>

#define N_NODES 100000
#define N_EDGES 1000000
#define D 64
#define CAP 64           // padded CSR slots/node (Poisson(10): P(deg>64)~1e-30; fallback exists)

// Scratch (device globals — no allocations allowed)
__device__ __align__(16) float g_mean[N_NODES * D];
__device__ int g_cnt[N_NODES];
__device__ __align__(16) int g_csr[N_NODES * CAP];

// ---------------------------------------------------------------------------
// Kernel 1: zero degree counters
// ---------------------------------------------------------------------------
__global__ __launch_bounds__(256) void zero_kernel() {
    const int i = blockIdx.x * 256 + threadIdx.x;
    if (i < N_NODES) g_cnt[i] = 0;
}

// ---------------------------------------------------------------------------
// Kernel 2: CSR fill (round-5 form: 1 edge/thread — measured faster than int2)
// ---------------------------------------------------------------------------
__global__ __launch_bounds__(256) void fill_kernel(const int* __restrict__ ei) {
    const int e = blockIdx.x * 256 + threadIdx.x;
    if (e >= N_EDGES) return;
    const int dst = __ldg(ei + N_EDGES + e);
    const int src = __ldg(ei + e);
    const int pos = atomicAdd(g_cnt + dst, 1);
    if (pos < CAP) g_csr[dst * CAP + pos] = src;
}

// ---------------------------------------------------------------------------
// Kernel 3: gather (round-5 form). Half-warp per node, LDG.128 streams,
// register accumulation, single mean-row write. Inline overflow fallback.
// ---------------------------------------------------------------------------
__global__ __launch_bounds__(256) void gather_kernel(const float* __restrict__ x,
                                                     const int* __restrict__ ei) {
    const int warp = blockIdx.x * 8 + (threadIdx.x >> 5);
    const int lane = threadIdx.x & 31;
    const int sub  = lane >> 4;
    const int j    = lane & 15;
    const int node = warp * 2 + sub;      // grid covers exactly N_NODES

    const int cnt  = g_cnt[node];
    const float r  = 1.0f / (float)(cnt > 1 ? cnt : 1);
    const float4* x4 = reinterpret_cast<const float4*>(x);

    float4 acc = make_float4(0.f, 0.f, 0.f, 0.f);
    if (cnt <= CAP) {
        const int4* row = reinterpret_cast<const int4*>(g_csr + node * CAP);
        for (int e0 = 0; e0 < cnt; e0 += 4) {
            const int4 s = __ldg(row + (e0 >> 2));   // broadcast in half-warp
            const int rem = cnt - e0;
            float4 v0 = __ldg(x4 + (size_t)s.x * 16 + j);
            float4 v1, v2, v3;
            if (rem > 1) v1 = __ldg(x4 + (size_t)s.y * 16 + j);
            if (rem > 2) v2 = __ldg(x4 + (size_t)s.z * 16 + j);
            if (rem > 3) v3 = __ldg(x4 + (size_t)s.w * 16 + j);
            acc.x += v0.x; acc.y += v0.y; acc.z += v0.z; acc.w += v0.w;
            if (rem > 1) { acc.x += v1.x; acc.y += v1.y; acc.z += v1.z; acc.w += v1.w; }
            if (rem > 2) { acc.x += v2.x; acc.y += v2.y; acc.z += v2.z; acc.w += v2.w; }
            if (rem > 3) { acc.x += v3.x; acc.y += v3.y; acc.z += v3.z; acc.w += v3.w; }
        }
    } else {
        for (int e = 0; e < N_EDGES; e++) {          // ~never taken
            if (__ldg(ei + N_EDGES + e) == node) {
                float4 v = __ldg(x4 + (size_t)__ldg(ei + e) * 16 + j);
                acc.x += v.x; acc.y += v.y; acc.z += v.z; acc.w += v.w;
            }
        }
    }
    acc.x *= r; acc.y *= r; acc.z *= r; acc.w *= r;
    reinterpret_cast<float4*>(g_mean)[(size_t)node * 16 + j] = acc;
}

// ---------------------------------------------------------------------------
// Kernel 4: out = relu([mean|x] @ [Wl;Wr]^T + b)  — single K=128 GEMM.
// 128 threads / block, 128 nodes / block. Thread tile: 8 nodes x 8 outputs.
// Per k: 64B LDS feeds 32 FFMA2 (2.0 B/FFMA2; was 3.0). Conflict-free
// staging (thread-per-node, same-k-across-warp writes).
// ---------------------------------------------------------------------------
#define WPAD 68      // 64 + 4
#define APAD 132     // 128 + 4
#define K2   128

__global__ __launch_bounds__(128, 2) void out_kernel(
    const float* __restrict__ x,
    const float* __restrict__ Wl,
    const float* __restrict__ bl,
    const float* __restrict__ Wr,
    float* __restrict__ out)
{
    extern __shared__ float sm[];
    float* sW  = sm;                        // [128][WPAD]  rows 0..63 = Wl k, 64..127 = Wr k
    float* sAX = sW + K2 * WPAD;            // [128][APAD]  rows 0..63 = mean k, 64..127 = x k

    const int tid = threadIdx.x;
    const int node0 = blockIdx.x * 128;

    // --- stage W: thread o (0..63) reads row o of Wl/Wr, writes k-major ---
    if (tid < 64) {
        const float4* wl4 = reinterpret_cast<const float4*>(Wl + tid * D);
        const float4* wr4 = reinterpret_cast<const float4*>(Wr + tid * D);
        #pragma unroll 4
        for (int kq = 0; kq < 16; kq++) {
            const float4 w = __ldg(wl4 + kq);
            const float4 u = __ldg(wr4 + kq);
            const int k = kq * 4;
            sW[(k+0)*WPAD + tid] = w.x; sW[(k+1)*WPAD + tid] = w.y;
            sW[(k+2)*WPAD + tid] = w.z; sW[(k+3)*WPAD + tid] = w.w;
            sW[(64+k+0)*WPAD + tid] = u.x; sW[(64+k+1)*WPAD + tid] = u.y;
            sW[(64+k+2)*WPAD + tid] = u.z; sW[(64+k+3)*WPAD + tid] = u.w;
        }
    }

    // --- stage AX: thread owns node0+tid; full-row reads, k-major writes ---
    {
        const int gn = node0 + tid;
        const bool ok = gn < N_NODES;
        const float4* m4 = reinterpret_cast<const float4*>(g_mean) + (size_t)(ok ? gn : 0) * 16;
        const float4* xv4 = reinterpret_cast<const float4*>(x)     + (size_t)(ok ? gn : 0) * 16;
        #pragma unroll 4
        for (int kq = 0; kq < 16; kq++) {
            float4 a = __ldg(m4 + kq);
            float4 v = __ldg(xv4 + kq);
            if (!ok) { a = make_float4(0.f,0.f,0.f,0.f); v = a; }
            const int k = kq * 4;
            sAX[(k+0)*APAD + tid] = a.x; sAX[(k+1)*APAD + tid] = a.y;
            sAX[(k+2)*APAD + tid] = a.z; sAX[(k+3)*APAD + tid] = a.w;
            sAX[(64+k+0)*APAD + tid] = v.x; sAX[(64+k+1)*APAD + tid] = v.y;
            sAX[(64+k+2)*APAD + tid] = v.z; sAX[(64+k+3)*APAD + tid] = v.w;
        }
    }
    __syncthreads();

    // --- GEMM: thread (tx 0..7, ty 0..15): outs ob..ob+7, nodes nb..nb+7 ---
    const int tx = tid & 7;
    const int ty = tid >> 3;
    const int ob = tx * 8;
    const int nb = ty * 8;

    unsigned long long acc[4][8];           // [node-pair][out], bias preloaded
    #pragma unroll
    for (int o = 0; o < 8; o++) {
        const float b = __ldg(bl + ob + o);
        unsigned long long bp;
        asm("mov.b64 %0, {%1, %2};" : "=l"(bp) : "f"(b), "f"(b));
        #pragma unroll
        for (int m = 0; m < 4; m++) acc[m][o] = bp;
    }

    #pragma unroll 4
    for (int k = 0; k < K2; k++) {
        const ulonglong2 aA = *reinterpret_cast<const ulonglong2*>(sAX + k*APAD + nb);
        const ulonglong2 aB = *reinterpret_cast<const ulonglong2*>(sAX + k*APAD + nb + 4);
        const float4 w0 = *reinterpret_cast<const float4*>(sW + k*WPAD + ob);
        const float4 w1 = *reinterpret_cast<const float4*>(sW + k*WPAD + ob + 4);
        const unsigned long long ap[4] = {aA.x, aA.y, aB.x, aB.y};
        const float wv[8] = {w0.x, w0.y, w0.z, w0.w, w1.x, w1.y, w1.z, w1.w};
        #pragma unroll
        for (int o = 0; o < 8; o++) {
            unsigned long long w2;
            asm("mov.b64 %0, {%1, %2};" : "=l"(w2) : "f"(wv[o]), "f"(wv[o]));
            #pragma unroll
            for (int m = 0; m < 4; m++)
                asm("fma.rn.f32x2 %0, %1, %2, %0;" : "+l"(acc[m][o]) : "l"(ap[m]), "l"(w2));
        }
    }

    // --- epilogue: ReLU + store (two float4 per node row) ---
    #pragma unroll
    for (int m = 0; m < 4; m++) {
        float lo[8], hi[8];
        #pragma unroll
        for (int o = 0; o < 8; o++)
            asm("mov.b64 {%0, %1}, %2;" : "=f"(lo[o]), "=f"(hi[o]) : "l"(acc[m][o]));
        const int g0 = node0 + nb + m * 2;
        if (g0 < N_NODES) {
            float4 v0 = make_float4(fmaxf(lo[0],0.f), fmaxf(lo[1],0.f),
                                    fmaxf(lo[2],0.f), fmaxf(lo[3],0.f));
            float4 v1 = make_float4(fmaxf(lo[4],0.f), fmaxf(lo[5],0.f),
                                    fmaxf(lo[6],0.f), fmaxf(lo[7],0.f));
            float4* po = reinterpret_cast<float4*>(out + (size_t)g0*D + ob);
            po[0] = v0; po[1] = v1;
        }
        if (g0 + 1 < N_NODES) {
            float4 v0 = make_float4(fmaxf(hi[0],0.f), fmaxf(hi[1],0.f),
                                    fmaxf(hi[2],0.f), fmaxf(hi[3],0.f));
            float4 v1 = make_float4(fmaxf(hi[4],0.f), fmaxf(hi[5],0.f),
                                    fmaxf(hi[6],0.f), fmaxf(hi[7],0.f));
            float4* po = reinterpret_cast<float4*>(out + (size_t)(g0+1)*D + ob);
            po[0] = v0; po[1] = v1;
        }
    }
}

// ---------------------------------------------------------------------------
extern "C" void kernel_launch(void* const* d_in, const int* in_sizes, int n_in,
                              void* d_out, int out_size)
{
    const float* x  = (const float*)d_in[0];
    const int*   ei = (const int*)d_in[1];     // int32 (JAX x64 disabled)
    const float* Wl = (const float*)d_in[2];
    const float* bl = (const float*)d_in[3];
    const float* Wr = (const float*)d_in[4];
    float* out = (float*)d_out;

    const int smem_bytes = (K2 * WPAD + K2 * APAD) * sizeof(float);   // ~102.5 KB
    cudaFuncSetAttribute(out_kernel, cudaFuncAttributeMaxDynamicSharedMemorySize, smem_bytes);

    zero_kernel<<<(N_NODES + 255) / 256, 256>>>();
    fill_kernel<<<(N_EDGES + 255) / 256, 256>>>(ei);
    gather_kernel<<<N_NODES / 16, 256>>>(x, ei);   // 2 nodes/warp * 8 warps
    out_kernel<<<(N_NODES + 127) / 128, 128, smem_bytes>>>(x, Wl, bl, Wr, out);
}